// round 12
// baseline (speedup 1.0000x reference)
#include <cuda_runtime.h>
#include <cuda_bf16.h>
#include <math_constants.h>
#include <cstdint>

#define NB     8
#define NQ     32
#define NTOK   1024
#define NDOCS  5000
#define DLEN   128
#define DIM    128
#define TOPK   100

// Scratch (no device allocation allowed)
__device__ int   g_flags[NB * NDOCS];
__device__ int   g_counts[NB];
__device__ int   g_upids[NB * NTOK];
__device__ float g_scores[NB * NTOK];

// ---- smem word-offset layout (uint32 words) ----
// V tiles: 128 rows x 64 words (word = bf16x2 pair). Q tiles: 32 rows x 64 words.
#define VHI_W  0
#define VLO_W  8192
#define QHI_W  16384
#define QLO_W  18432
#define D_W    20480          // f32 [128][33]
#define SMEM_WORDS (D_W + 128 * 33)
#define SMEM_BYTES (SMEM_WORDS * 4)   // 98816

// swizzled word index for (row r, pair p) in a 64-word row
__device__ __forceinline__ int W(int r, int p) {
    return r * 64 + (p ^ ((r & 7) << 2));
}

// mma.sync m16n8k16 row.col f32.bf16.bf16.f32 (sm_80+ portable HMMA)
__device__ __forceinline__ void mma_bf16(float* c, const uint32_t* a,
                                         const uint32_t* b) {
    asm volatile(
        "mma.sync.aligned.m16n8k16.row.col.f32.bf16.bf16.f32 "
        "{%0,%1,%2,%3}, {%4,%5,%6,%7}, {%8,%9}, {%0,%1,%2,%3};"
        : "+f"(c[0]), "+f"(c[1]), "+f"(c[2]), "+f"(c[3])
        : "r"(a[0]), "r"(a[1]), "r"(a[2]), "r"(a[3]), "r"(b[0]), "r"(b[1]));
}

// ---------------------------------------------------------------- init
__global__ void init_kernel() {
    int i = blockIdx.x * blockDim.x + threadIdx.x;
    if (i < NB * NDOCS) g_flags[i] = 0;
    if (i < NB * NTOK) {
        g_scores[i] = -CUDART_INF_F;
        g_upids[i]  = -1;
    }
    if (i < NB) g_counts[i] = 0;
}

// ---------------------------------------------------------------- mark unique pids
__global__ void mark_kernel(const int* __restrict__ token_ids,
                            const int* __restrict__ emb2pid) {
    int i = blockIdx.x * blockDim.x + threadIdx.x;
    if (i >= NB * NTOK) return;
    int b = i >> 10;
    int tok = token_ids[i];
    if (tok < 0 || tok >= NDOCS * DLEN) return;
    int pid = emb2pid[tok];
    if (pid < 0 || pid >= NDOCS) return;
    if (atomicExch(&g_flags[b * NDOCS + pid], 1) == 0) {
        int pos = atomicAdd(&g_counts[b], 1);
        g_upids[b * NTOK + pos] = pid;
    }
}

// ---------------------------------------------------------------- MaxSim score
// Split-bf16 HMMA: D = Vhi@Qhi^T + Vhi@Qlo^T + Vlo@Qhi^T, fp32 accum.
// One 128-thread block per (b, pid); warp w owns token rows [w*32, w*32+32).
__global__ __launch_bounds__(128) void score_kernel(
        const float* __restrict__ q_vectors,   // [NB, NQ, DIM]
        const float* __restrict__ vectors) {   // [NDOCS, DLEN, DIM]
    int b   = blockIdx.y;
    int idx = blockIdx.x;
    if (idx >= g_counts[b]) return;
    int pid = g_upids[b * NTOK + idx];

    extern __shared__ uint32_t S[];
    float* Df = (float*)(S + D_W);
    int tid = threadIdx.x;
    int wid = tid >> 5, lane = tid & 31;

    // ---- convert V row `tid` (128 f32 -> 64 hi pairs + 64 lo pairs)
    {
        const float4* vp = (const float4*)(vectors + ((size_t)pid * DLEN + tid) * DIM);
#pragma unroll 8
        for (int k4 = 0; k4 < 32; k4++) {
            float4 x = vp[k4];
            __nv_bfloat162 h01 = __floats2bfloat162_rn(x.x, x.y);
            __nv_bfloat162 h23 = __floats2bfloat162_rn(x.z, x.w);
            __nv_bfloat162 l01 = __floats2bfloat162_rn(x.x - __bfloat162float(h01.x),
                                                       x.y - __bfloat162float(h01.y));
            __nv_bfloat162 l23 = __floats2bfloat162_rn(x.z - __bfloat162float(h23.x),
                                                       x.w - __bfloat162float(h23.y));
            int p = 2 * k4;
            S[VHI_W + W(tid, p)]     = *(uint32_t*)&h01;
            S[VHI_W + W(tid, p + 1)] = *(uint32_t*)&h23;
            S[VLO_W + W(tid, p)]     = *(uint32_t*)&l01;
            S[VLO_W + W(tid, p + 1)] = *(uint32_t*)&l23;
        }
    }
    // ---- convert Q: thread -> (row tid/4, k-quarter tid%4)
    {
        int qr = tid >> 2, kq = tid & 3;
        const float4* qp = (const float4*)(q_vectors + (size_t)b * NQ * DIM +
                                           qr * DIM + kq * 32);
#pragma unroll
        for (int j = 0; j < 8; j++) {
            float4 x = qp[j];
            __nv_bfloat162 h01 = __floats2bfloat162_rn(x.x, x.y);
            __nv_bfloat162 h23 = __floats2bfloat162_rn(x.z, x.w);
            __nv_bfloat162 l01 = __floats2bfloat162_rn(x.x - __bfloat162float(h01.x),
                                                       x.y - __bfloat162float(h01.y));
            __nv_bfloat162 l23 = __floats2bfloat162_rn(x.z - __bfloat162float(h23.x),
                                                       x.w - __bfloat162float(h23.y));
            int p = kq * 16 + 2 * j;
            S[QHI_W + W(qr, p)]     = *(uint32_t*)&h01;
            S[QHI_W + W(qr, p + 1)] = *(uint32_t*)&h23;
            S[QLO_W + W(qr, p)]     = *(uint32_t*)&l01;
            S[QLO_W + W(qr, p + 1)] = *(uint32_t*)&l23;
        }
    }
    __syncthreads();

    // ---- per-warp MMA: D[32 tok x 32 q]
    float acc[2][4][4];
#pragma unroll
    for (int m = 0; m < 2; m++)
#pragma unroll
        for (int n = 0; n < 4; n++)
#pragma unroll
            for (int i = 0; i < 4; i++) acc[m][n][i] = 0.f;

    int tq = lane >> 2, tr = lane & 3;   // fragment row/col groups
    int gr = wid * 32;                   // warp token base

#pragma unroll
    for (int kt = 0; kt < 8; kt++) {
        int p0 = tr + kt * 8;
        uint32_t bh[4][2], bl[4][2];
#pragma unroll
        for (int n = 0; n < 4; n++) {
            int qr = n * 8 + tq;
            bh[n][0] = S[QHI_W + W(qr, p0)];
            bh[n][1] = S[QHI_W + W(qr, p0 + 4)];
            bl[n][0] = S[QLO_W + W(qr, p0)];
            bl[n][1] = S[QLO_W + W(qr, p0 + 4)];
        }
#pragma unroll
        for (int m = 0; m < 2; m++) {
            int ar = gr + m * 16 + tq;
            uint32_t ah[4] = { S[VHI_W + W(ar, p0)],     S[VHI_W + W(ar + 8, p0)],
                               S[VHI_W + W(ar, p0 + 4)], S[VHI_W + W(ar + 8, p0 + 4)] };
            uint32_t al[4] = { S[VLO_W + W(ar, p0)],     S[VLO_W + W(ar + 8, p0)],
                               S[VLO_W + W(ar, p0 + 4)], S[VLO_W + W(ar + 8, p0 + 4)] };
#pragma unroll
            for (int n = 0; n < 4; n++) {
                mma_bf16(acc[m][n], ah, bh[n]);
                mma_bf16(acc[m][n], ah, bl[n]);
                mma_bf16(acc[m][n], al, bh[n]);
            }
        }
    }

    // ---- stash D tile to smem (rows padded to 33 floats)
#pragma unroll
    for (int m = 0; m < 2; m++)
#pragma unroll
        for (int n = 0; n < 4; n++) {
            int r0 = gr + m * 16 + tq, c0 = n * 8 + tr * 2;
            Df[r0 * 33 + c0]           = acc[m][n][0];
            Df[r0 * 33 + c0 + 1]       = acc[m][n][1];
            Df[(r0 + 8) * 33 + c0]     = acc[m][n][2];
            Df[(r0 + 8) * 33 + c0 + 1] = acc[m][n][3];
        }
    __syncthreads();

    // ---- max over tokens, sum over q (thread = token row)
    __shared__ float wmax[4][NQ];
    const float* Drow = Df + tid * 33;
#pragma unroll
    for (int q = 0; q < NQ; q++) {
        float m = Drow[q];
#pragma unroll
        for (int off = 16; off; off >>= 1)
            m = fmaxf(m, __shfl_xor_sync(0xffffffffu, m, off));
        if (lane == 0) wmax[wid][q] = m;
    }
    __syncthreads();
    if (wid == 0) {
        float m = fmaxf(fmaxf(wmax[0][lane], wmax[1][lane]),
                        fmaxf(wmax[2][lane], wmax[3][lane]));
#pragma unroll
        for (int off = 16; off; off >>= 1)
            m += __shfl_xor_sync(0xffffffffu, m, off);
        if (lane == 0) g_scores[b * NTOK + idx] = m;
    }
}

// ---------------------------------------------------------------- top-k (bitonic)
__global__ __launch_bounds__(NTOK) void topk_kernel(float* __restrict__ out) {
    __shared__ unsigned long long keys[NTOK];
    int b = blockIdx.x, tid = threadIdx.x;

    float s = g_scores[b * NTOK + tid];
    unsigned int bits = __float_as_uint(s);
    unsigned int u = (bits & 0x80000000u) ? ~bits : (bits | 0x80000000u);
    keys[tid] = ~(((unsigned long long)u << 32) | (unsigned int)tid);
    __syncthreads();

    for (int k = 2; k <= NTOK; k <<= 1) {
        for (int j = k >> 1; j > 0; j >>= 1) {
            int ixj = tid ^ j;
            if (ixj > tid) {
                unsigned long long a = keys[tid], c = keys[ixj];
                bool up = ((tid & k) == 0);
                if ((a > c) == up) { keys[tid] = c; keys[ixj] = a; }
            }
            __syncthreads();
        }
    }

    if (tid < TOPK) {
        int idx = (int)(~keys[tid] & 0xFFFFFFFFull);
        out[b * TOPK + tid]             = g_scores[b * NTOK + idx];
        out[NB * TOPK + b * TOPK + tid] = (float)g_upids[b * NTOK + idx];
    }
}

// ---------------------------------------------------------------- launch
extern "C" void kernel_launch(void* const* d_in, const int* in_sizes, int n_in,
                              void* d_out, int out_size) {
    const float* q_vectors = nullptr;
    const int*   token_ids = nullptr;
    const float* vectors   = nullptr;
    const int*   emb2pid   = nullptr;
    for (int i = 0; i < n_in; i++) {
        long long sz = in_sizes[i];
        if (sz == NB * NQ * DIM)              q_vectors = (const float*)d_in[i];
        else if (sz == NB * NTOK)             token_ids = (const int*)d_in[i];
        else if (sz == (long long)NDOCS * DLEN * DIM) vectors = (const float*)d_in[i];
        else if (sz == (long long)NDOCS * DLEN)       emb2pid = (const int*)d_in[i];
    }

    float* out = (float*)d_out;

    cudaFuncSetAttribute(score_kernel,
                         cudaFuncAttributeMaxDynamicSharedMemorySize, SMEM_BYTES);

    int init_n = NB * NDOCS;
    init_kernel<<<(init_n + 255) / 256, 256>>>();
    mark_kernel<<<(NB * NTOK + 255) / 256, 256>>>(token_ids, emb2pid);
    dim3 sgrid(NTOK, NB);
    score_kernel<<<sgrid, 128, SMEM_BYTES>>>(q_vectors, vectors);
    topk_kernel<<<NB, NTOK>>>(out);
    (void)out_size;
}

// round 13
// speedup vs baseline: 1.2663x; 1.2663x over previous
#include <cuda_runtime.h>
#include <cuda_bf16.h>
#include <math_constants.h>
#include <cstdint>

#define NB     8
#define NQ     32
#define NTOK   1024
#define NDOCS  5000
#define DLEN   128
#define DIM    128
#define TOPK   100

// Scratch (no device allocation allowed)
__device__ int   g_flags[NB * NDOCS];
__device__ int   g_counts[NB];
__device__ int   g_upids[NB * NTOK];
__device__ float g_scores[NB * NTOK];
__device__ int   g_dused[NDOCS];
__device__ int   g_dcount;
__device__ int   g_dlist[NDOCS];
// Pre-converted tiles, already in the swizzled smem word layout.
// [doc][0]=hi plane, [doc][1]=lo plane; 8192 words (128 rows x 64 bf16x2 words)
__device__ __align__(16) uint32_t g_vconv[NDOCS][2][8192];   // ~328 MB
__device__ __align__(16) uint32_t g_qconv[NB][2][2048];      // 32 rows x 64 words

// ---- smem word-offset layout (uint32 words) ----
#define VHI_W  0
#define VLO_W  8192
#define QHI_W  16384
#define QLO_W  18432
#define D_W    20480          // f32 [128][33]
#define SMEM_WORDS (D_W + 128 * 33)
#define SMEM_BYTES (SMEM_WORDS * 4)   // 98816

// swizzled word index for (row r, pair p) in a 64-word row
__device__ __forceinline__ int W(int r, int p) {
    return r * 64 + (p ^ ((r & 7) << 2));
}

__device__ __forceinline__ uint32_t smem_u32(const void* p) {
    uint32_t a;
    asm("{ .reg .u64 t; cvta.to.shared.u64 t, %1; cvt.u32.u64 %0, t; }"
        : "=r"(a) : "l"(p));
    return a;
}

// mma.sync m16n8k16 row.col f32.bf16.bf16.f32 (sm_80+ portable HMMA)
__device__ __forceinline__ void mma_bf16(float* c, const uint32_t* a,
                                         const uint32_t* b) {
    asm volatile(
        "mma.sync.aligned.m16n8k16.row.col.f32.bf16.bf16.f32 "
        "{%0,%1,%2,%3}, {%4,%5,%6,%7}, {%8,%9}, {%0,%1,%2,%3};"
        : "+f"(c[0]), "+f"(c[1]), "+f"(c[2]), "+f"(c[3])
        : "r"(a[0]), "r"(a[1]), "r"(a[2]), "r"(a[3]), "r"(b[0]), "r"(b[1]));
}

// split one float4 into hi/lo bf16x2 words
__device__ __forceinline__ void split4(float4 x, uint32_t& h01, uint32_t& h23,
                                       uint32_t& l01, uint32_t& l23) {
    __nv_bfloat162 h0 = __floats2bfloat162_rn(x.x, x.y);
    __nv_bfloat162 h2 = __floats2bfloat162_rn(x.z, x.w);
    __nv_bfloat162 l0 = __floats2bfloat162_rn(x.x - __bfloat162float(h0.x),
                                              x.y - __bfloat162float(h0.y));
    __nv_bfloat162 l2 = __floats2bfloat162_rn(x.z - __bfloat162float(h2.x),
                                              x.w - __bfloat162float(h2.y));
    h01 = *(uint32_t*)&h0; h23 = *(uint32_t*)&h2;
    l01 = *(uint32_t*)&l0; l23 = *(uint32_t*)&l2;
}

// ---------------------------------------------------------------- init
__global__ void init_kernel() {
    int i = blockIdx.x * blockDim.x + threadIdx.x;
    if (i < NB * NDOCS) g_flags[i] = 0;
    if (i < NB * NTOK) {
        g_scores[i] = -CUDART_INF_F;
        g_upids[i]  = -1;
    }
    if (i < NB) g_counts[i] = 0;
    if (i < NDOCS) g_dused[i] = 0;
    if (i == 0) g_dcount = 0;
}

// ---------------------------------------------------------------- mark unique pids
__global__ void mark_kernel(const int* __restrict__ token_ids,
                            const int* __restrict__ emb2pid) {
    int i = blockIdx.x * blockDim.x + threadIdx.x;
    if (i >= NB * NTOK) return;
    int b = i >> 10;
    int tok = token_ids[i];
    if (tok < 0 || tok >= NDOCS * DLEN) return;
    int pid = emb2pid[tok];
    if (pid < 0 || pid >= NDOCS) return;
    if (atomicExch(&g_flags[b * NDOCS + pid], 1) == 0) {
        int pos = atomicAdd(&g_counts[b], 1);
        g_upids[b * NTOK + pos] = pid;
        if (atomicExch(&g_dused[pid], 1) == 0) {
            int dp = atomicAdd(&g_dcount, 1);
            g_dlist[dp] = pid;
        }
    }
}

// ---------------------------------------------------------------- Q pre-convert
__global__ __launch_bounds__(128) void qconv_kernel(
        const float* __restrict__ q_vectors) {
    int b = blockIdx.x, tid = threadIdx.x;
    int qr = tid >> 2, kq = tid & 3;
    const float4* qp = (const float4*)(q_vectors + (size_t)b * NQ * DIM +
                                       qr * DIM + kq * 32);
#pragma unroll
    for (int j = 0; j < 8; j++) {
        uint32_t h01, h23, l01, l23;
        split4(qp[j], h01, h23, l01, l23);
        int w = W(qr, kq * 16 + 2 * j);   // even p -> w, w+1 adjacent
        *(uint2*)&g_qconv[b][0][w] = make_uint2(h01, h23);
        *(uint2*)&g_qconv[b][1][w] = make_uint2(l01, l23);
    }
}

// ---------------------------------------------------------------- V pre-convert
// One block per used doc; chunk-linear mapping -> coalesced LDG and STG.
__global__ __launch_bounds__(128) void vconv_kernel(
        const float* __restrict__ vectors) {
    int i = blockIdx.x;
    if (i >= g_dcount) return;
    int doc = g_dlist[i];
    int tid = threadIdx.x;
    uint32_t* dh = g_vconv[doc][0];
    uint32_t* dl = g_vconv[doc][1];
#pragma unroll 4
    for (int k = 0; k < 16; k++) {
        int c    = tid + k * 128;         // chunk 0..2047 (16B granule)
        int row  = c >> 4;
        int colb = (c & 15) * 8;          // element col base (8 f32)
        const float4* vp = (const float4*)(vectors +
                           ((size_t)doc * DLEN + row) * DIM + colb);
        uint32_t h0, h1, h2, h3, l0, l1, l2, l3;
        split4(vp[0], h0, h1, l0, l1);
        split4(vp[1], h2, h3, l2, l3);
        int w = row * 64 + (((c & 15) * 4) ^ ((row & 7) << 2));
        *(uint4*)(dh + w) = make_uint4(h0, h1, h2, h3);
        *(uint4*)(dl + w) = make_uint4(l0, l1, l2, l3);
    }
}

// ---------------------------------------------------------------- MaxSim score
// cp.async bulk copy of pre-converted tiles, then split-bf16 HMMA:
// D = Vhi@Qhi^T + Vhi@Qlo^T + Vlo@Qhi^T, fp32 accum.
__global__ __launch_bounds__(128) void score_kernel() {
    int b   = blockIdx.y;
    int idx = blockIdx.x;
    if (idx >= g_counts[b]) return;
    int pid = g_upids[b * NTOK + idx];

    extern __shared__ uint32_t S[];
    float* Df = (float*)(S + D_W);
    int tid = threadIdx.x;
    int wid = tid >> 5, lane = tid & 31;
    uint32_t sb = smem_u32(S);

    // ---- async copy: V hi+lo (16384 words) then Q hi+lo (4096 words)
    {
        const uint4* vsrc = (const uint4*)&g_vconv[pid][0][0];
        const uint4* qsrc = (const uint4*)&g_qconv[b][0][0];
#pragma unroll
        for (int k = 0; k < 32; k++) {
            uint32_t d = sb + (uint32_t)(tid + k * 128) * 16u;
            asm volatile("cp.async.ca.shared.global [%0], [%1], 16;"
                         :: "r"(d), "l"(vsrc + tid + k * 128));
        }
#pragma unroll
        for (int k = 0; k < 8; k++) {
            uint32_t d = sb + (uint32_t)QHI_W * 4u + (uint32_t)(tid + k * 128) * 16u;
            asm volatile("cp.async.ca.shared.global [%0], [%1], 16;"
                         :: "r"(d), "l"(qsrc + tid + k * 128));
        }
        asm volatile("cp.async.commit_group;");
        asm volatile("cp.async.wait_group 0;" ::: "memory");
    }
    __syncthreads();

    // ---- per-warp MMA: D[32 tok x 32 q]
    float acc[2][4][4];
#pragma unroll
    for (int m = 0; m < 2; m++)
#pragma unroll
        for (int n = 0; n < 4; n++)
#pragma unroll
            for (int i = 0; i < 4; i++) acc[m][n][i] = 0.f;

    int tq = lane >> 2, tr = lane & 3;
    int gr = wid * 32;

#pragma unroll
    for (int kt = 0; kt < 8; kt++) {
        int p0 = tr + kt * 8;
        uint32_t bh[4][2], bl[4][2];
#pragma unroll
        for (int n = 0; n < 4; n++) {
            int qr = n * 8 + tq;
            bh[n][0] = S[QHI_W + W(qr, p0)];
            bh[n][1] = S[QHI_W + W(qr, p0 + 4)];
            bl[n][0] = S[QLO_W + W(qr, p0)];
            bl[n][1] = S[QLO_W + W(qr, p0 + 4)];
        }
#pragma unroll
        for (int m = 0; m < 2; m++) {
            int ar = gr + m * 16 + tq;
            uint32_t ah[4] = { S[VHI_W + W(ar, p0)],     S[VHI_W + W(ar + 8, p0)],
                               S[VHI_W + W(ar, p0 + 4)], S[VHI_W + W(ar + 8, p0 + 4)] };
            uint32_t al[4] = { S[VLO_W + W(ar, p0)],     S[VLO_W + W(ar + 8, p0)],
                               S[VLO_W + W(ar, p0 + 4)], S[VLO_W + W(ar + 8, p0 + 4)] };
#pragma unroll
            for (int n = 0; n < 4; n++) {
                mma_bf16(acc[m][n], ah, bh[n]);
                mma_bf16(acc[m][n], ah, bl[n]);
                mma_bf16(acc[m][n], al, bh[n]);
            }
        }
    }

    // ---- stash D tile to smem (rows padded to 33 floats)
#pragma unroll
    for (int m = 0; m < 2; m++)
#pragma unroll
        for (int n = 0; n < 4; n++) {
            int r0 = gr + m * 16 + tq, c0 = n * 8 + tr * 2;
            Df[r0 * 33 + c0]           = acc[m][n][0];
            Df[r0 * 33 + c0 + 1]       = acc[m][n][1];
            Df[(r0 + 8) * 33 + c0]     = acc[m][n][2];
            Df[(r0 + 8) * 33 + c0 + 1] = acc[m][n][3];
        }
    __syncthreads();

    // ---- max over tokens, sum over q (thread = token row)
    __shared__ float wmax[4][NQ];
    const float* Drow = Df + tid * 33;
#pragma unroll
    for (int q = 0; q < NQ; q++) {
        float m = Drow[q];
#pragma unroll
        for (int off = 16; off; off >>= 1)
            m = fmaxf(m, __shfl_xor_sync(0xffffffffu, m, off));
        if (lane == 0) wmax[wid][q] = m;
    }
    __syncthreads();
    if (wid == 0) {
        float m = fmaxf(fmaxf(wmax[0][lane], wmax[1][lane]),
                        fmaxf(wmax[2][lane], wmax[3][lane]));
#pragma unroll
        for (int off = 16; off; off >>= 1)
            m += __shfl_xor_sync(0xffffffffu, m, off);
        if (lane == 0) g_scores[b * NTOK + idx] = m;
    }
}

// ---------------------------------------------------------------- top-k (bitonic)
__global__ __launch_bounds__(NTOK) void topk_kernel(float* __restrict__ out) {
    __shared__ unsigned long long keys[NTOK];
    int b = blockIdx.x, tid = threadIdx.x;

    float s = g_scores[b * NTOK + tid];
    unsigned int bits = __float_as_uint(s);
    unsigned int u = (bits & 0x80000000u) ? ~bits : (bits | 0x80000000u);
    keys[tid] = ~(((unsigned long long)u << 32) | (unsigned int)tid);
    __syncthreads();

    for (int k = 2; k <= NTOK; k <<= 1) {
        for (int j = k >> 1; j > 0; j >>= 1) {
            int ixj = tid ^ j;
            if (ixj > tid) {
                unsigned long long a = keys[tid], c = keys[ixj];
                bool up = ((tid & k) == 0);
                if ((a > c) == up) { keys[tid] = c; keys[ixj] = a; }
            }
            __syncthreads();
        }
    }

    if (tid < TOPK) {
        int idx = (int)(~keys[tid] & 0xFFFFFFFFull);
        out[b * TOPK + tid]             = g_scores[b * NTOK + idx];
        out[NB * TOPK + b * TOPK + tid] = (float)g_upids[b * NTOK + idx];
    }
}

// ---------------------------------------------------------------- launch
extern "C" void kernel_launch(void* const* d_in, const int* in_sizes, int n_in,
                              void* d_out, int out_size) {
    const float* q_vectors = nullptr;
    const int*   token_ids = nullptr;
    const float* vectors   = nullptr;
    const int*   emb2pid   = nullptr;
    for (int i = 0; i < n_in; i++) {
        long long sz = in_sizes[i];
        if (sz == NB * NQ * DIM)              q_vectors = (const float*)d_in[i];
        else if (sz == NB * NTOK)             token_ids = (const int*)d_in[i];
        else if (sz == (long long)NDOCS * DLEN * DIM) vectors = (const float*)d_in[i];
        else if (sz == (long long)NDOCS * DLEN)       emb2pid = (const int*)d_in[i];
    }

    float* out = (float*)d_out;

    cudaFuncSetAttribute(score_kernel,
                         cudaFuncAttributeMaxDynamicSharedMemorySize, SMEM_BYTES);

    int init_n = NB * NDOCS;
    init_kernel<<<(init_n + 255) / 256, 256>>>();
    mark_kernel<<<(NB * NTOK + 255) / 256, 256>>>(token_ids, emb2pid);
    qconv_kernel<<<NB, 128>>>(q_vectors);
    vconv_kernel<<<NDOCS, 128>>>(vectors);
    dim3 sgrid(NTOK, NB);
    score_kernel<<<sgrid, 128, SMEM_BYTES>>>();
    topk_kernel<<<NB, NTOK>>>(out);
    (void)out_size;
}

// round 15
// speedup vs baseline: 1.7380x; 1.3725x over previous
#include <cuda_runtime.h>
#include <cuda_bf16.h>
#include <math_constants.h>
#include <cstdint>

#define NB     8
#define NQ     32
#define NTOK   1024
#define NDOCS  5000
#define DLEN   128
#define DIM    128
#define TOPK   100
#define CH     8          // pids per score block

// Scratch (no device allocation allowed)
__device__ int   g_flags[NB * NDOCS];
__device__ int   g_counts[NB];
__device__ int   g_upids[NB * NTOK];
__device__ float g_scores[NB * NTOK];
__device__ int   g_dused[NDOCS];
__device__ int   g_dcount;
__device__ int   g_dlist[NDOCS];
// Pre-converted tiles in the swizzled smem word layout.
// [doc][0]=hi plane, [doc][1]=lo plane; 8192 words each pair of planes
__device__ __align__(16) uint32_t g_vconv[NDOCS][2][8192];
__device__ __align__(16) uint32_t g_qconv[NB][2][2048];

// score-kernel smem word layout: Q hi (2048) + Q lo (2048) + V bufs (2 x 16384)
#define QW     0
#define VW0    4096
#define VBUFW  16384
#define SMEM_WORDS (VW0 + 2 * VBUFW)
#define SMEM_BYTES (SMEM_WORDS * 4)    // 147456 = 144KB

// swizzled word index for (row r, pair p) in a 64-word row
__device__ __forceinline__ int W(int r, int p) {
    return r * 64 + (p ^ ((r & 7) << 2));
}

__device__ __forceinline__ uint32_t smem_u32(const void* p) {
    uint32_t a;
    asm("{ .reg .u64 t; cvta.to.shared.u64 t, %1; cvt.u32.u64 %0, t; }"
        : "=r"(a) : "l"(p));
    return a;
}

// mma.sync m16n8k16 row.col f32.bf16.bf16.f32
__device__ __forceinline__ void mma_bf16(float* c, const uint32_t* a,
                                         const uint32_t* b) {
    asm volatile(
        "mma.sync.aligned.m16n8k16.row.col.f32.bf16.bf16.f32 "
        "{%0,%1,%2,%3}, {%4,%5,%6,%7}, {%8,%9}, {%0,%1,%2,%3};"
        : "+f"(c[0]), "+f"(c[1]), "+f"(c[2]), "+f"(c[3])
        : "r"(a[0]), "r"(a[1]), "r"(a[2]), "r"(a[3]), "r"(b[0]), "r"(b[1]));
}

__device__ __forceinline__ void split4(float4 x, uint32_t& h01, uint32_t& h23,
                                       uint32_t& l01, uint32_t& l23) {
    __nv_bfloat162 h0 = __floats2bfloat162_rn(x.x, x.y);
    __nv_bfloat162 h2 = __floats2bfloat162_rn(x.z, x.w);
    __nv_bfloat162 l0 = __floats2bfloat162_rn(x.x - __bfloat162float(h0.x),
                                              x.y - __bfloat162float(h0.y));
    __nv_bfloat162 l2 = __floats2bfloat162_rn(x.z - __bfloat162float(h2.x),
                                              x.w - __bfloat162float(h2.y));
    h01 = *(uint32_t*)&h0; h23 = *(uint32_t*)&h2;
    l01 = *(uint32_t*)&l0; l23 = *(uint32_t*)&l2;
}

// ---------------------------------------------------------------- init
__global__ void init_kernel() {
    int i = blockIdx.x * blockDim.x + threadIdx.x;
    if (i < NB * NDOCS) g_flags[i] = 0;
    if (i < NB * NTOK) {
        g_scores[i] = -CUDART_INF_F;
        g_upids[i]  = -1;
    }
    if (i < NB) g_counts[i] = 0;
    if (i < NDOCS) g_dused[i] = 0;
    if (i == 0) g_dcount = 0;
}

// ---------------------------------------------------------------- mark unique pids
__global__ void mark_kernel(const int* __restrict__ token_ids,
                            const int* __restrict__ emb2pid) {
    int i = blockIdx.x * blockDim.x + threadIdx.x;
    if (i >= NB * NTOK) return;
    int b = i >> 10;
    int tok = token_ids[i];
    if (tok < 0 || tok >= NDOCS * DLEN) return;
    int pid = emb2pid[tok];
    if (pid < 0 || pid >= NDOCS) return;
    if (atomicExch(&g_flags[b * NDOCS + pid], 1) == 0) {
        int pos = atomicAdd(&g_counts[b], 1);
        g_upids[b * NTOK + pos] = pid;
        if (atomicExch(&g_dused[pid], 1) == 0) {
            int dp = atomicAdd(&g_dcount, 1);
            g_dlist[dp] = pid;
        }
    }
}

// ---------------------------------------------------------------- Q pre-convert
__global__ __launch_bounds__(128) void qconv_kernel(
        const float* __restrict__ q_vectors) {
    int b = blockIdx.x, tid = threadIdx.x;
    int qr = tid >> 2, kq = tid & 3;
    const float4* qp = (const float4*)(q_vectors + (size_t)b * NQ * DIM +
                                       qr * DIM + kq * 32);
#pragma unroll
    for (int j = 0; j < 8; j++) {
        uint32_t h01, h23, l01, l23;
        split4(qp[j], h01, h23, l01, l23);
        int w = W(qr, kq * 16 + 2 * j);
        *(uint2*)&g_qconv[b][0][w] = make_uint2(h01, h23);
        *(uint2*)&g_qconv[b][1][w] = make_uint2(l01, l23);
    }
}

// ---------------------------------------------------------------- V pre-convert
__global__ __launch_bounds__(128) void vconv_kernel(
        const float* __restrict__ vectors) {
    int i = blockIdx.x;
    if (i >= g_dcount) return;
    int doc = g_dlist[i];
    int tid = threadIdx.x;
    uint32_t* dh = g_vconv[doc][0];
    uint32_t* dl = g_vconv[doc][1];
#pragma unroll 4
    for (int k = 0; k < 16; k++) {
        int c    = tid + k * 128;
        int row  = c >> 4;
        int colb = (c & 15) * 8;
        const float4* vp = (const float4*)(vectors +
                           ((size_t)doc * DLEN + row) * DIM + colb);
        uint32_t h0, h1, h2, h3, l0, l1, l2, l3;
        split4(vp[0], h0, h1, l0, l1);
        split4(vp[1], h2, h3, l2, l3);
        int w = row * 64 + (((c & 15) * 4) ^ ((row & 7) << 2));
        *(uint4*)(dh + w) = make_uint4(h0, h1, h2, h3);
        *(uint4*)(dl + w) = make_uint4(l0, l1, l2, l3);
    }
}

// ---------------------------------------------------------------- MaxSim score
// 256 threads, CH pids per block, double-buffered cp.async V prefetch.
// Warp w owns token rows [16w, 16w+16). Register epilogue (no D smem tile).
__global__ __launch_bounds__(256) void score_kernel() {
    int b    = blockIdx.y;
    int cnt  = g_counts[b];
    int base = blockIdx.x * CH;
    if (base >= cnt) return;

    extern __shared__ uint32_t S[];
    __shared__ float wmax[8][NQ];
    int tid = threadIdx.x;
    int wid = tid >> 5, lane = tid & 31;
    uint32_t sb = smem_u32(S);

    // group 0: Q (hi+lo, 1024 uint4) + V[pid0] (4096 uint4)
    {
        const uint4* qsrc = (const uint4*)&g_qconv[b][0][0];
#pragma unroll
        for (int k = 0; k < 4; k++) {
            uint32_t d = sb + (uint32_t)(tid + k * 256) * 16u;
            asm volatile("cp.async.ca.shared.global [%0], [%1], 16;"
                         :: "r"(d), "l"(qsrc + tid + k * 256));
        }
        int pid0 = g_upids[b * NTOK + base];
        const uint4* vsrc = (const uint4*)&g_vconv[pid0][0][0];
#pragma unroll
        for (int k = 0; k < 16; k++) {
            uint32_t d = sb + (uint32_t)VW0 * 4u + (uint32_t)(tid + k * 256) * 16u;
            asm volatile("cp.async.ca.shared.global [%0], [%1], 16;"
                         :: "r"(d), "l"(vsrc + tid + k * 256));
        }
        asm volatile("cp.async.commit_group;");
    }

    int tq = lane >> 2, tr = lane & 3;

    for (int i = 0; i < CH; i++) {
        int idx = base + i;
        if (idx >= cnt) break;

        bool hasnext = (i + 1 < CH) && (idx + 1 < cnt);
        if (hasnext) {
            int pidn = g_upids[b * NTOK + idx + 1];
            const uint4* vsrc = (const uint4*)&g_vconv[pidn][0][0];
            uint32_t vb = (uint32_t)(VW0 + ((i + 1) & 1) * VBUFW) * 4u;
#pragma unroll
            for (int k = 0; k < 16; k++) {
                uint32_t d = sb + vb + (uint32_t)(tid + k * 256) * 16u;
                asm volatile("cp.async.ca.shared.global [%0], [%1], 16;"
                             :: "r"(d), "l"(vsrc + tid + k * 256));
            }
            asm volatile("cp.async.commit_group;");
            asm volatile("cp.async.wait_group 1;" ::: "memory");
        } else {
            asm volatile("cp.async.wait_group 0;" ::: "memory");
        }
        __syncthreads();

        const uint32_t* Vh = S + VW0 + (i & 1) * VBUFW;
        const uint32_t* Vl = Vh + 8192;
        const uint32_t* Qh = S + QW;
        const uint32_t* Ql = S + QW + 2048;

        float acc[4][4];
#pragma unroll
        for (int n = 0; n < 4; n++)
#pragma unroll
            for (int j = 0; j < 4; j++) acc[n][j] = 0.f;

        int ar = wid * 16 + tq;
#pragma unroll
        for (int kt = 0; kt < 8; kt++) {
            int p0 = tr + kt * 8;
            uint32_t bh[4][2], bl[4][2];
#pragma unroll
            for (int n = 0; n < 4; n++) {
                int qr = n * 8 + tq;
                bh[n][0] = Qh[W(qr, p0)];
                bh[n][1] = Qh[W(qr, p0 + 4)];
                bl[n][0] = Ql[W(qr, p0)];
                bl[n][1] = Ql[W(qr, p0 + 4)];
            }
            uint32_t ah[4] = { Vh[W(ar, p0)],     Vh[W(ar + 8, p0)],
                               Vh[W(ar, p0 + 4)], Vh[W(ar + 8, p0 + 4)] };
            uint32_t al[4] = { Vl[W(ar, p0)],     Vl[W(ar + 8, p0)],
                               Vl[W(ar, p0 + 4)], Vl[W(ar + 8, p0 + 4)] };
#pragma unroll
            for (int n = 0; n < 4; n++) {
                mma_bf16(acc[n], ah, bh[n]);
                mma_bf16(acc[n], ah, bl[n]);
                mma_bf16(acc[n], al, bh[n]);
            }
        }

        // ---- register epilogue: max over this warp's 16 token rows
        // acc[n][0],[1]: row ar, cols n*8+tr*2, +1 ; acc[n][2],[3]: row ar+8
#pragma unroll
        for (int n = 0; n < 4; n++) {
            float c0 = fmaxf(acc[n][0], acc[n][2]);
            float c1 = fmaxf(acc[n][1], acc[n][3]);
            // reduce max over tq (lane bits 2..4)
#pragma unroll
            for (int off = 4; off <= 16; off <<= 1) {
                c0 = fmaxf(c0, __shfl_xor_sync(0xffffffffu, c0, off));
                c1 = fmaxf(c1, __shfl_xor_sync(0xffffffffu, c1, off));
            }
            if (tq == 0) {
                wmax[wid][n * 8 + tr * 2]     = c0;
                wmax[wid][n * 8 + tr * 2 + 1] = c1;
            }
        }
        __syncthreads();
        if (wid == 0) {
            float m = wmax[0][lane];
#pragma unroll
            for (int w = 1; w < 8; w++) m = fmaxf(m, wmax[w][lane]);
#pragma unroll
            for (int off = 16; off; off >>= 1)
                m += __shfl_xor_sync(0xffffffffu, m, off);
            if (lane == 0) g_scores[b * NTOK + idx] = m;
        }
        __syncthreads();
    }
}

// ---------------------------------------------------------------- top-k (bitonic)
__global__ __launch_bounds__(NTOK) void topk_kernel(float* __restrict__ out) {
    __shared__ unsigned long long keys[NTOK];
    int b = blockIdx.x, tid = threadIdx.x;

    float s = g_scores[b * NTOK + tid];
    unsigned int bits = __float_as_uint(s);
    unsigned int u = (bits & 0x80000000u) ? ~bits : (bits | 0x80000000u);
    keys[tid] = ~(((unsigned long long)u << 32) | (unsigned int)tid);
    __syncthreads();

    for (int k = 2; k <= NTOK; k <<= 1) {
        for (int j = k >> 1; j > 0; j >>= 1) {
            int ixj = tid ^ j;
            if (ixj > tid) {
                unsigned long long a = keys[tid], c = keys[ixj];
                bool up = ((tid & k) == 0);
                if ((a > c) == up) { keys[tid] = c; keys[ixj] = a; }
            }
            __syncthreads();
        }
    }

    if (tid < TOPK) {
        int idx = (int)(~keys[tid] & 0xFFFFFFFFull);
        out[b * TOPK + tid]             = g_scores[b * NTOK + idx];
        out[NB * TOPK + b * TOPK + tid] = (float)g_upids[b * NTOK + idx];
    }
}

// ---------------------------------------------------------------- launch
extern "C" void kernel_launch(void* const* d_in, const int* in_sizes, int n_in,
                              void* d_out, int out_size) {
    const float* q_vectors = nullptr;
    const int*   token_ids = nullptr;
    const float* vectors   = nullptr;
    const int*   emb2pid   = nullptr;
    for (int i = 0; i < n_in; i++) {
        long long sz = in_sizes[i];
        if (sz == NB * NQ * DIM)              q_vectors = (const float*)d_in[i];
        else if (sz == NB * NTOK)             token_ids = (const int*)d_in[i];
        else if (sz == (long long)NDOCS * DLEN * DIM) vectors = (const float*)d_in[i];
        else if (sz == (long long)NDOCS * DLEN)       emb2pid = (const int*)d_in[i];
    }

    float* out = (float*)d_out;

    cudaFuncSetAttribute(score_kernel,
                         cudaFuncAttributeMaxDynamicSharedMemorySize, SMEM_BYTES);

    int init_n = NB * NDOCS;
    init_kernel<<<(init_n + 255) / 256, 256>>>();
    mark_kernel<<<(NB * NTOK + 255) / 256, 256>>>(token_ids, emb2pid);
    qconv_kernel<<<NB, 128>>>(q_vectors);
    vconv_kernel<<<NDOCS, 128>>>(vectors);
    dim3 sgrid(NTOK / CH, NB);
    score_kernel<<<sgrid, 256, SMEM_BYTES>>>();
    topk_kernel<<<NB, NTOK>>>(out);
    (void)out_size;
}

// round 16
// speedup vs baseline: 1.9008x; 1.0937x over previous
#include <cuda_runtime.h>
#include <cuda_bf16.h>
#include <math_constants.h>
#include <cstdint>

#define NB     8
#define NQ     32
#define NTOK   1024
#define NDOCS  5000
#define DLEN   128
#define DIM    128
#define TOPK   100
#define DPB    8          // docs per score block

// Scratch (no device allocation allowed)
__device__ int   g_flags[NB * NDOCS];
__device__ int   g_slot[NB * NDOCS];    // slot+1 of pid in batch's unique list
__device__ int   g_counts[NB];
__device__ int   g_upids[NB * NTOK];
__device__ float g_scores[NB * NTOK];
__device__ int   g_dused[NDOCS];
__device__ int   g_dcount;
__device__ int   g_dlist[NDOCS];
__device__ __align__(16) uint32_t g_qconv[NB][2][2048];  // Q hi/lo planes

// ---- score-kernel smem word layout ----
// QW: 4096 words (Qhi 2048 + Qlo 2048)   = 16 KB
// FW: 2 x 16384 f32 words (double buf)   = 128 KB
// VH/VL: 8192 + 8192 words               = 64 KB
#define QW     0
#define FW     4096
#define FBUFW  16384
#define VH     36864
#define VL     45056
#define SMEM_WORDS 53248
#define SMEM_BYTES (SMEM_WORDS * 4)   // 212992 B = 208 KB

// swizzled word index for (row r, pair p) in a 64-word row
__device__ __forceinline__ int W(int r, int p) {
    return r * 64 + (p ^ ((r & 7) << 2));
}

__device__ __forceinline__ uint32_t smem_u32(const void* p) {
    uint32_t a;
    asm("{ .reg .u64 t; cvta.to.shared.u64 t, %1; cvt.u32.u64 %0, t; }"
        : "=r"(a) : "l"(p));
    return a;
}

// mma.sync m16n8k16 row.col f32.bf16.bf16.f32
__device__ __forceinline__ void mma_bf16(float* c, const uint32_t* a,
                                         const uint32_t* b) {
    asm volatile(
        "mma.sync.aligned.m16n8k16.row.col.f32.bf16.bf16.f32 "
        "{%0,%1,%2,%3}, {%4,%5,%6,%7}, {%8,%9}, {%0,%1,%2,%3};"
        : "+f"(c[0]), "+f"(c[1]), "+f"(c[2]), "+f"(c[3])
        : "r"(a[0]), "r"(a[1]), "r"(a[2]), "r"(a[3]), "r"(b[0]), "r"(b[1]));
}

__device__ __forceinline__ void split4(float4 x, uint32_t& h01, uint32_t& h23,
                                       uint32_t& l01, uint32_t& l23) {
    __nv_bfloat162 h0 = __floats2bfloat162_rn(x.x, x.y);
    __nv_bfloat162 h2 = __floats2bfloat162_rn(x.z, x.w);
    __nv_bfloat162 l0 = __floats2bfloat162_rn(x.x - __bfloat162float(h0.x),
                                              x.y - __bfloat162float(h0.y));
    __nv_bfloat162 l2 = __floats2bfloat162_rn(x.z - __bfloat162float(h2.x),
                                              x.w - __bfloat162float(h2.y));
    h01 = *(uint32_t*)&h0; h23 = *(uint32_t*)&h2;
    l01 = *(uint32_t*)&l0; l23 = *(uint32_t*)&l2;
}

// ---------------------------------------------------------------- init
__global__ void init_kernel() {
    int i = blockIdx.x * blockDim.x + threadIdx.x;
    if (i < NB * NDOCS) { g_flags[i] = 0; g_slot[i] = 0; }
    if (i < NB * NTOK) {
        g_scores[i] = -CUDART_INF_F;
        g_upids[i]  = -1;
    }
    if (i < NB) g_counts[i] = 0;
    if (i < NDOCS) g_dused[i] = 0;
    if (i == 0) g_dcount = 0;
}

// ---------------------------------------------------------------- mark unique pids
__global__ void mark_kernel(const int* __restrict__ token_ids,
                            const int* __restrict__ emb2pid) {
    int i = blockIdx.x * blockDim.x + threadIdx.x;
    if (i >= NB * NTOK) return;
    int b = i >> 10;
    int tok = token_ids[i];
    if (tok < 0 || tok >= NDOCS * DLEN) return;
    int pid = emb2pid[tok];
    if (pid < 0 || pid >= NDOCS) return;
    if (atomicExch(&g_flags[b * NDOCS + pid], 1) == 0) {
        int pos = atomicAdd(&g_counts[b], 1);
        g_upids[b * NTOK + pos] = pid;
        g_slot[b * NDOCS + pid] = pos + 1;
        if (atomicExch(&g_dused[pid], 1) == 0) {
            int dp = atomicAdd(&g_dcount, 1);
            g_dlist[dp] = pid;
        }
    }
}

// ---------------------------------------------------------------- Q pre-convert
__global__ __launch_bounds__(128) void qconv_kernel(
        const float* __restrict__ q_vectors) {
    int b = blockIdx.x, tid = threadIdx.x;
    int qr = tid >> 2, kq = tid & 3;
    const float4* qp = (const float4*)(q_vectors + (size_t)b * NQ * DIM +
                                       qr * DIM + kq * 32);
#pragma unroll
    for (int j = 0; j < 8; j++) {
        uint32_t h01, h23, l01, l23;
        split4(qp[j], h01, h23, l01, l23);
        int w = W(qr, kq * 16 + 2 * j);
        *(uint2*)&g_qconv[b][0][w] = make_uint2(h01, h23);
        *(uint2*)&g_qconv[b][1][w] = make_uint2(l01, l23);
    }
}

// ---------------------------------------------------------------- fused score
// Doc-major: block owns DPB docs. Per doc: async f32 fill (double-buffered) ->
// in-smem split-convert (once) -> MMA for every batch using the doc.
__global__ __launch_bounds__(256) void score_kernel(
        const float* __restrict__ vectors) {
    int dcount = g_dcount;
    int base = blockIdx.x * DPB;
    if (base >= dcount) return;

    extern __shared__ uint32_t S[];
    __shared__ float wmax[8][NQ];
    __shared__ int bslot[8];
    int tid = threadIdx.x;
    int wid = tid >> 5, lane = tid & 31;
    uint32_t sb = smem_u32(S);
    int tq = lane >> 2, tr = lane & 3;
    int ar = wid * 16 + tq;

    // prefetch f32 tile of first doc into fbuf0
    {
        int d0 = g_dlist[base];
        const uint4* src = (const uint4*)(vectors + (size_t)d0 * DLEN * DIM);
#pragma unroll
        for (int k = 0; k < 16; k++) {
            uint32_t d = sb + (uint32_t)FW * 4u + (uint32_t)(tid + k * 256) * 16u;
            asm volatile("cp.async.ca.shared.global [%0], [%1], 16;"
                         :: "r"(d), "l"(src + tid + k * 256));
        }
        asm volatile("cp.async.commit_group;");
    }

    for (int i = 0; i < DPB; i++) {
        int di = base + i;
        if (di >= dcount) break;
        int doc = g_dlist[di];

        bool hasnext = (i + 1 < DPB) && (di + 1 < dcount);
        if (hasnext) {
            int dn = g_dlist[di + 1];
            const uint4* src = (const uint4*)(vectors + (size_t)dn * DLEN * DIM);
            uint32_t fb = (uint32_t)(FW + ((i + 1) & 1) * FBUFW) * 4u;
#pragma unroll
            for (int k = 0; k < 16; k++) {
                uint32_t d = sb + fb + (uint32_t)(tid + k * 256) * 16u;
                asm volatile("cp.async.ca.shared.global [%0], [%1], 16;"
                             :: "r"(d), "l"(src + tid + k * 256));
            }
            asm volatile("cp.async.commit_group;");
            asm volatile("cp.async.wait_group 1;" ::: "memory");
        } else {
            asm volatile("cp.async.wait_group 0;" ::: "memory");
        }
        __syncthreads();   // fbuf[i&1] ready; prev doc's MMA done (epilogue sync)

        // ---- convert f32 tile -> VH/VL (warp-uniform row, conflict-free)
        {
            const float4* F = (const float4*)(S + FW + (i & 1) * FBUFW);
#pragma unroll
            for (int k = 0; k < 16; k++) {
                int idx4 = tid + k * 256;        // 0..4095
                float4 x = F[idx4];
                uint32_t h01, h23, l01, l23;
                split4(x, h01, h23, l01, l23);
                int row = idx4 >> 5, p = (idx4 & 31) * 2;
                int w = W(row, p);
                *(uint2*)&S[VH + w] = make_uint2(h01, h23);
                *(uint2*)&S[VL + w] = make_uint2(l01, l23);
            }
        }
        if (tid < NB) bslot[tid] = g_slot[tid * NDOCS + doc];
        __syncthreads();

        // ---- first active batch; preload its Q into regs
        int nb = 8;
#pragma unroll
        for (int b = 7; b >= 0; b--) if (bslot[b]) nb = b;

        uint4 q0, q1, q2, q3;
        {
            const uint4* qs = (const uint4*)&g_qconv[nb][0][0];
            q0 = qs[tid]; q1 = qs[tid + 256]; q2 = qs[tid + 512]; q3 = qs[tid + 768];
        }

        while (nb < 8) {
            int cur = nb;
            nb = 8;
            for (int b = cur + 1; b < 8; b++) if (bslot[b]) { nb = b; break; }

            // stage Q into smem
            ((uint4*)S)[tid]       = q0;
            ((uint4*)S)[tid + 256] = q1;
            ((uint4*)S)[tid + 512] = q2;
            ((uint4*)S)[tid + 768] = q3;
            __syncthreads();

            // prefetch next batch's Q (overlaps MMA)
            if (nb < 8) {
                const uint4* qs = (const uint4*)&g_qconv[nb][0][0];
                q0 = qs[tid]; q1 = qs[tid + 256]; q2 = qs[tid + 512]; q3 = qs[tid + 768];
            }

            const uint32_t* Vh = S + VH;
            const uint32_t* Vl = S + VL;
            const uint32_t* Qh = S + QW;
            const uint32_t* Ql = S + QW + 2048;

            float acc[4][4];
#pragma unroll
            for (int n = 0; n < 4; n++)
#pragma unroll
                for (int j = 0; j < 4; j++) acc[n][j] = 0.f;

#pragma unroll
            for (int kt = 0; kt < 8; kt++) {
                int p0 = tr + kt * 8;
                uint32_t bh[4][2], bl[4][2];
#pragma unroll
                for (int n = 0; n < 4; n++) {
                    int qr = n * 8 + tq;
                    bh[n][0] = Qh[W(qr, p0)];
                    bh[n][1] = Qh[W(qr, p0 + 4)];
                    bl[n][0] = Ql[W(qr, p0)];
                    bl[n][1] = Ql[W(qr, p0 + 4)];
                }
                uint32_t ah[4] = { Vh[W(ar, p0)],     Vh[W(ar + 8, p0)],
                                   Vh[W(ar, p0 + 4)], Vh[W(ar + 8, p0 + 4)] };
                uint32_t al[4] = { Vl[W(ar, p0)],     Vl[W(ar + 8, p0)],
                                   Vl[W(ar, p0 + 4)], Vl[W(ar + 8, p0 + 4)] };
#pragma unroll
                for (int n = 0; n < 4; n++) {
                    mma_bf16(acc[n], ah, bh[n]);
                    mma_bf16(acc[n], ah, bl[n]);
                    mma_bf16(acc[n], al, bh[n]);
                }
            }

            // ---- register epilogue: max over this warp's 16 token rows
#pragma unroll
            for (int n = 0; n < 4; n++) {
                float c0 = fmaxf(acc[n][0], acc[n][2]);
                float c1 = fmaxf(acc[n][1], acc[n][3]);
#pragma unroll
                for (int off = 4; off <= 16; off <<= 1) {
                    c0 = fmaxf(c0, __shfl_xor_sync(0xffffffffu, c0, off));
                    c1 = fmaxf(c1, __shfl_xor_sync(0xffffffffu, c1, off));
                }
                if (tq == 0) {
                    wmax[wid][n * 8 + tr * 2]     = c0;
                    wmax[wid][n * 8 + tr * 2 + 1] = c1;
                }
            }
            __syncthreads();
            if (wid == 0) {
                float m = wmax[0][lane];
#pragma unroll
                for (int w = 1; w < 8; w++) m = fmaxf(m, wmax[w][lane]);
#pragma unroll
                for (int off = 16; off; off >>= 1)
                    m += __shfl_xor_sync(0xffffffffu, m, off);
                if (lane == 0)
                    g_scores[cur * NTOK + bslot[cur] - 1] = m;
            }
            __syncthreads();
        }
    }
}

// ---------------------------------------------------------------- top-k (bitonic)
__global__ __launch_bounds__(NTOK) void topk_kernel(float* __restrict__ out) {
    __shared__ unsigned long long keys[NTOK];
    int b = blockIdx.x, tid = threadIdx.x;

    float s = g_scores[b * NTOK + tid];
    unsigned int bits = __float_as_uint(s);
    unsigned int u = (bits & 0x80000000u) ? ~bits : (bits | 0x80000000u);
    keys[tid] = ~(((unsigned long long)u << 32) | (unsigned int)tid);
    __syncthreads();

    for (int k = 2; k <= NTOK; k <<= 1) {
        for (int j = k >> 1; j > 0; j >>= 1) {
            int ixj = tid ^ j;
            if (ixj > tid) {
                unsigned long long a = keys[tid], c = keys[ixj];
                bool up = ((tid & k) == 0);
                if ((a > c) == up) { keys[tid] = c; keys[ixj] = a; }
            }
            __syncthreads();
        }
    }

    if (tid < TOPK) {
        int idx = (int)(~keys[tid] & 0xFFFFFFFFull);
        out[b * TOPK + tid]             = g_scores[b * NTOK + idx];
        out[NB * TOPK + b * TOPK + tid] = (float)g_upids[b * NTOK + idx];
    }
}

// ---------------------------------------------------------------- launch
extern "C" void kernel_launch(void* const* d_in, const int* in_sizes, int n_in,
                              void* d_out, int out_size) {
    const float* q_vectors = nullptr;
    const int*   token_ids = nullptr;
    const float* vectors   = nullptr;
    const int*   emb2pid   = nullptr;
    for (int i = 0; i < n_in; i++) {
        long long sz = in_sizes[i];
        if (sz == NB * NQ * DIM)              q_vectors = (const float*)d_in[i];
        else if (sz == NB * NTOK)             token_ids = (const int*)d_in[i];
        else if (sz == (long long)NDOCS * DLEN * DIM) vectors = (const float*)d_in[i];
        else if (sz == (long long)NDOCS * DLEN)       emb2pid = (const int*)d_in[i];
    }

    float* out = (float*)d_out;

    cudaFuncSetAttribute(score_kernel,
                         cudaFuncAttributeMaxDynamicSharedMemorySize, SMEM_BYTES);

    int init_n = NB * NDOCS;
    init_kernel<<<(init_n + 255) / 256, 256>>>();
    mark_kernel<<<(NB * NTOK + 255) / 256, 256>>>(token_ids, emb2pid);
    qconv_kernel<<<NB, 128>>>(q_vectors);
    score_kernel<<<(NDOCS + DPB - 1) / DPB, 256, SMEM_BYTES>>>(vectors);
    topk_kernel<<<NB, NTOK>>>(out);
    (void)out_size;
}